// round 1
// baseline (speedup 1.0000x reference)
#include <cuda_runtime.h>
#include <math.h>

// NoisyTopKRouter: B=4, S=4096, D=2048, E=64, K=8
// out layout assumed: probs [B*S*E] f32, topk_idx [B*S*K] (as f32), new_bias [E] f32

namespace {

constexpr int T_TOK  = 16384;   // B*S
constexpr int D      = 2048;
constexpr int E      = 64;
constexpr int KSEL   = 8;
constexpr int TILE_T = 64;      // tokens per block
constexpr int KC     = 32;      // K chunk

__global__ __launch_bounds__(256, 3)
void router_kernel(const float* __restrict__ x,
                   const float* __restrict__ Wr,
                   const float* __restrict__ Wn,
                   const float* __restrict__ bias,
                   const float* __restrict__ nu,
                   float* __restrict__ out_probs,
                   float* __restrict__ out_idx,
                   float* __restrict__ out_bias)
{
    __shared__ float xs[TILE_T][KC];     // x tile, [token][k]
    __shared__ float ws[KC][129];        // W tile, [k][expert 0..127], +1 pad
    __shared__ float zs[TILE_T][E + 1];  // z values for top-k

    const int tid = threadIdx.x;
    const int tx  = tid & 15;    // expert group
    const int ty  = tid >> 4;    // token group
    const int token0 = blockIdx.x * TILE_T;

    float acc[4][8];
#pragma unroll
    for (int i = 0; i < 4; i++)
#pragma unroll
        for (int j = 0; j < 8; j++) acc[i][j] = 0.f;

    for (int k0 = 0; k0 < D; k0 += KC) {
        // ---- load x tile: 64 tokens x 32 k = 512 float4, 2 per thread ----
#pragma unroll
        for (int r = 0; r < 2; r++) {
            int idx = tid + r * 256;
            int t = idx >> 3, kq = idx & 7;
            float4 v = *reinterpret_cast<const float4*>(
                &x[(size_t)(token0 + t) * D + k0 + kq * 4]);
            *reinterpret_cast<float4*>(&xs[t][kq * 4]) = v;
        }
        // ---- load W tile: 128 rows (Wr|Wn) x 32 k = 1024 float4, 4/thread ----
#pragma unroll
        for (int r = 0; r < 4; r++) {
            int idx = tid + r * 256;
            int e = idx >> 3, kq = idx & 7;
            const float* src = (e < 64) ? (Wr + (size_t)e * D)
                                        : (Wn + (size_t)(e - 64) * D);
            float4 v = *reinterpret_cast<const float4*>(&src[k0 + kq * 4]);
            ws[kq * 4 + 0][e] = v.x;
            ws[kq * 4 + 1][e] = v.y;
            ws[kq * 4 + 2][e] = v.z;
            ws[kq * 4 + 3][e] = v.w;
        }
        __syncthreads();

        // ---- 64x128 tile FMA, 4x8 per thread ----
#pragma unroll 8
        for (int k = 0; k < KC; k++) {
            float rx[4], rw[8];
#pragma unroll
            for (int i = 0; i < 4; i++) rx[i] = xs[ty + 16 * i][k];
#pragma unroll
            for (int j = 0; j < 8; j++) rw[j] = ws[k][tx + 16 * j];
#pragma unroll
            for (int i = 0; i < 4; i++)
#pragma unroll
                for (int j = 0; j < 8; j++)
                    acc[i][j] = fmaf(rx[i], rw[j], acc[i][j]);
        }
        __syncthreads();
    }

    // ---- epilogue: z = noise_u * softplus(noisy) + logit + bias ----
    // acc[i][j] j<4: Wr (logits) for expert e=tx+16j; j>=4: Wn for same e.
#pragma unroll
    for (int i = 0; i < 4; i++) {
        int tl = ty + 16 * i;
        size_t t = (size_t)token0 + tl;
#pragma unroll
        for (int j = 0; j < 4; j++) {
            int e = tx + 16 * j;
            float logit = acc[i][j];
            float noisy = acc[i][j + 4];
            float u = nu[t * E + e];
            float sp = fmaxf(noisy, 0.f) + log1pf(expf(-fabsf(noisy)));
            zs[tl][e] = fmaf(u, sp, logit + bias[e]);
        }
    }
    __syncthreads();

    // ---- top-8 + softmax, one warp per token (8 tokens per warp) ----
    const int lane = tid & 31;
    const int warp = tid >> 5;
    for (int r = 0; r < 8; r++) {
        int tl = warp * 8 + r;
        size_t t = (size_t)token0 + tl;
        float z0 = zs[tl][lane];
        float z1 = zs[tl][lane + 32];
        float v0 = z0, v1 = z1;
        int sel0 = 0, sel1 = 0;
        float m0 = 0.f, denom = 0.f;
        int myidx = 0;
#pragma unroll
        for (int k = 0; k < KSEL; k++) {
            // local best of two (tie -> lower index = v0)
            float bv; int bi;
            if (v0 >= v1) { bv = v0; bi = lane; }
            else          { bv = v1; bi = lane + 32; }
            // warp reduce: max value, tie -> lowest index (jax top_k semantics)
#pragma unroll
            for (int off = 16; off > 0; off >>= 1) {
                float ov = __shfl_xor_sync(0xffffffffu, bv, off);
                int   oi = __shfl_xor_sync(0xffffffffu, bi, off);
                if (ov > bv || (ov == bv && oi < bi)) { bv = ov; bi = oi; }
            }
            if (k == 0) m0 = bv;
            denom += expf(bv - m0);
            if (lane == k) myidx = bi;
            if (bi == lane)           { v0 = -1e30f; sel0 = 1; }
            else if (bi == lane + 32) { v1 = -1e30f; sel1 = 1; }
        }
        float inv = 1.f / denom;
        out_probs[t * E + lane]      = sel0 ? expf(z0 - m0) * inv : 0.f;
        out_probs[t * E + lane + 32] = sel1 ? expf(z1 - m0) * inv : 0.f;
        if (lane < KSEL) out_idx[t * KSEL + lane] = (float)myidx;
    }

    // ---- bias update: sign(avg - total_selected) == -1 always ----
    if (blockIdx.x == 0 && tid < E) out_bias[tid] = bias[tid] - 0.001f;
}

} // namespace

extern "C" void kernel_launch(void* const* d_in, const int* in_sizes, int n_in,
                              void* d_out, int out_size)
{
    (void)in_sizes; (void)n_in; (void)out_size;
    const float* x    = (const float*)d_in[0];
    const float* Wr   = (const float*)d_in[1];
    const float* Wn   = (const float*)d_in[2];
    const float* bias = (const float*)d_in[3];
    const float* nu   = (const float*)d_in[4];

    float* out   = (float*)d_out;
    float* probs = out;                                   // T*E
    float* idx   = out + (size_t)T_TOK * E;               // T*K
    float* nb    = idx + (size_t)T_TOK * KSEL;            // E

    router_kernel<<<T_TOK / TILE_T, 256>>>(x, Wr, Wn, bias, nu, probs, idx, nb);
}

// round 2
// speedup vs baseline: 1.0965x; 1.0965x over previous
#include <cuda_runtime.h>
#include <math.h>

// NoisyTopKRouter: B=4, S=4096, D=2048, E=64, K=8
// out: probs [T*E] f32, topk_idx [T*K] f32, new_bias [E] f32

namespace {

constexpr int T_TOK  = 16384;
constexpr int D      = 2048;
constexpr int E      = 64;
constexpr int KSEL   = 8;
constexpr int TILE_T = 64;
constexpr int KC     = 32;
constexpr int NTHR   = 128;
constexpr int NCHUNK = D / KC;   // 64

__device__ __forceinline__ void ffma2(unsigned long long& d,
                                      unsigned long long a,
                                      unsigned long long b) {
    asm("fma.rn.f32x2 %0, %1, %2, %0;" : "+l"(d) : "l"(a), "l"(b));
}

__global__ __launch_bounds__(NTHR)
void router_kernel(const float* __restrict__ x,
                   const float* __restrict__ Wr,
                   const float* __restrict__ Wn,
                   const float* __restrict__ bias,
                   const float* __restrict__ nu,
                   float* __restrict__ out_probs,
                   float* __restrict__ out_idx,
                   float* __restrict__ out_bias)
{
    // xs: x duplicated per token -> (x,x) pairs.  row = k, col = 2*t (+pad 2)
    __shared__ float xs[KC][2 * TILE_T + 2];
    // ws: interleaved (Wr[e], Wn[e]) pairs.      row = k, col = 2*e + s (+pad 2)
    __shared__ float ws[KC][2 * E + 2];
    // zs overlays xs after the mainloop: 64 x 65 = 4160 <= 32*130
    float (*zs)[E + 1] = reinterpret_cast<float (*)[E + 1]>(&xs[0][0]);

    const int tid = threadIdx.x;
    const int tx  = tid & 15;    // expert-pair group: experts e = tx + 16j, j=0..3
    const int ty  = tid >> 4;    // token group: tokens t = ty + 8i, i=0..7
    const int token0 = blockIdx.x * TILE_T;

    unsigned long long acc[8][4];
#pragma unroll
    for (int i = 0; i < 8; i++)
#pragma unroll
        for (int j = 0; j < 4; j++) acc[i][j] = 0ull;

    // ---- global-load helper state (register prefetch, 1 chunk ahead) ----
    float4 xv[4];   // x:  64 tok x 32 k = 512 float4 -> 4 / thread
    float4 wv[8];   // W: 128 row x 32 k = 1024 float4 -> 8 / thread

    auto ldg_chunk = [&](int k0) {
#pragma unroll
        for (int r = 0; r < 4; r++) {
            int idx = tid + r * NTHR;
            int t = idx >> 3, kq = idx & 7;
            xv[r] = *reinterpret_cast<const float4*>(
                &x[(size_t)(token0 + t) * D + k0 + kq * 4]);
        }
#pragma unroll
        for (int r = 0; r < 8; r++) {
            int idx = tid + r * NTHR;
            int row = idx >> 3, kq = idx & 7;       // row = 2e + s
            int e = row >> 1;
            const float* src = (row & 1) ? (Wn + (size_t)e * D)
                                         : (Wr + (size_t)e * D);
            wv[r] = *reinterpret_cast<const float4*>(&src[k0 + kq * 4]);
        }
    };

    ldg_chunk(0);

    for (int c = 0; c < NCHUNK; c++) {
        // ---- commit prefetched chunk to smem ----
#pragma unroll
        for (int r = 0; r < 4; r++) {
            int idx = tid + r * NTHR;
            int t = idx >> 3, kq = idx & 7;
            float4 v = xv[r];
            *reinterpret_cast<float2*>(&xs[kq * 4 + 0][2 * t]) = make_float2(v.x, v.x);
            *reinterpret_cast<float2*>(&xs[kq * 4 + 1][2 * t]) = make_float2(v.y, v.y);
            *reinterpret_cast<float2*>(&xs[kq * 4 + 2][2 * t]) = make_float2(v.z, v.z);
            *reinterpret_cast<float2*>(&xs[kq * 4 + 3][2 * t]) = make_float2(v.w, v.w);
        }
#pragma unroll
        for (int r = 0; r < 8; r++) {
            int idx = tid + r * NTHR;
            int row = idx >> 3, kq = idx & 7;
            float4 v = wv[r];
            ws[kq * 4 + 0][row] = v.x;
            ws[kq * 4 + 1][row] = v.y;
            ws[kq * 4 + 2][row] = v.z;
            ws[kq * 4 + 3][row] = v.w;
        }
        __syncthreads();

        // ---- issue next chunk's LDGs before compute (latency overlap) ----
        if (c + 1 < NCHUNK) ldg_chunk((c + 1) * KC);

        // ---- 64x128 tile, packed f32x2 FMA: 8 tok x 4 expert-pairs / thread ----
#pragma unroll 4
        for (int k = 0; k < KC; k++) {
            unsigned long long xp[8], wp[4];
#pragma unroll
            for (int i = 0; i < 8; i++)
                xp[i] = *reinterpret_cast<const unsigned long long*>(
                    &xs[k][2 * (ty + 8 * i)]);
#pragma unroll
            for (int j = 0; j < 4; j++)
                wp[j] = *reinterpret_cast<const unsigned long long*>(
                    &ws[k][2 * (tx + 16 * j)]);
#pragma unroll
            for (int i = 0; i < 8; i++)
#pragma unroll
                for (int j = 0; j < 4; j++)
                    ffma2(acc[i][j], xp[i], wp[j]);
        }
        __syncthreads();   // readers done before next store (and before zs overlay)
    }

    // ---- epilogue: z = noise_u * softplus(noisy) + logit + bias ----
    // acc[i][j]: lo = Wr dot (logit), hi = Wn dot (noisy), expert e = tx+16j
#pragma unroll
    for (int i = 0; i < 8; i++) {
        int tl = ty + 8 * i;
        size_t t = (size_t)token0 + tl;
#pragma unroll
        for (int j = 0; j < 4; j++) {
            int e = tx + 16 * j;
            float logit = __uint_as_float((unsigned)(acc[i][j] & 0xffffffffull));
            float noisy = __uint_as_float((unsigned)(acc[i][j] >> 32));
            float u = nu[t * E + e];
            float sp = fmaxf(noisy, 0.f) + log1pf(expf(-fabsf(noisy)));
            zs[tl][e] = fmaf(u, sp, logit + bias[e]);
        }
    }
    __syncthreads();

    // ---- top-8 + softmax: one warp per token, 16 tokens per warp ----
    const int lane = tid & 31;
    const int warp = tid >> 5;
    for (int r = 0; r < 16; r++) {
        int tl = warp * 16 + r;
        size_t t = (size_t)token0 + tl;
        float z0 = zs[tl][lane];
        float z1 = zs[tl][lane + 32];
        float v0 = z0, v1 = z1;
        int sel0 = 0, sel1 = 0;
        float m0 = 0.f, denom = 0.f;
        int myidx = 0;
#pragma unroll
        for (int k = 0; k < KSEL; k++) {
            float bv; int bi;
            if (v0 >= v1) { bv = v0; bi = lane; }
            else          { bv = v1; bi = lane + 32; }
#pragma unroll
            for (int off = 16; off > 0; off >>= 1) {
                float ov = __shfl_xor_sync(0xffffffffu, bv, off);
                int   oi = __shfl_xor_sync(0xffffffffu, bi, off);
                if (ov > bv || (ov == bv && oi < bi)) { bv = ov; bi = oi; }
            }
            if (k == 0) m0 = bv;
            denom += expf(bv - m0);
            if (lane == k) myidx = bi;
            if (bi == lane)           { v0 = -1e30f; sel0 = 1; }
            else if (bi == lane + 32) { v1 = -1e30f; sel1 = 1; }
        }
        float inv = 1.f / denom;
        out_probs[t * E + lane]      = sel0 ? expf(z0 - m0) * inv : 0.f;
        out_probs[t * E + lane + 32] = sel1 ? expf(z1 - m0) * inv : 0.f;
        if (lane < KSEL) out_idx[t * KSEL + lane] = (float)myidx;
    }

    // ---- bias update: sign(avg_load - total_selected) == -1 always ----
    if (blockIdx.x == 0 && tid < E) out_bias[tid] = bias[tid] - 0.001f;
}

} // namespace

extern "C" void kernel_launch(void* const* d_in, const int* in_sizes, int n_in,
                              void* d_out, int out_size)
{
    (void)in_sizes; (void)n_in; (void)out_size;
    const float* x    = (const float*)d_in[0];
    const float* Wr   = (const float*)d_in[1];
    const float* Wn   = (const float*)d_in[2];
    const float* bias = (const float*)d_in[3];
    const float* nu   = (const float*)d_in[4];

    float* out   = (float*)d_out;
    float* probs = out;
    float* idx   = out + (size_t)T_TOK * E;
    float* nb    = idx + (size_t)T_TOK * KSEL;

    router_kernel<<<T_TOK / TILE_T, NTHR>>>(x, Wr, Wn, bias, nu, probs, idx, nb);
}